// round 12
// baseline (speedup 1.0000x reference)
#include <cuda_runtime.h>
#include <cuda_bf16.h>
#include <cstdint>

// Problem constants
#define B_  2
#define T_  2048
#define D_  1024
#define H_  16
#define DH_ 64
#define TOPK_ 32
#define BH_ (B_*H_)

// Packed fp32x2 FMA
#define FMA_F32X2(d, a, b, c) \
    asm("fma.rn.f32x2 %0, %1, %2, %3;" : "=l"(d) : "l"(a), "l"(b), "l"(c))
#define PACK_DUP_F32X2(out, v) \
    asm("mov.b64 %0, {%1, %1};" : "=l"(out) : "r"(__float_as_uint(v)))
#define UNPACK_F32X2_(lo, hi, in) \
    asm("mov.b64 {%0, %1}, %2;" : "=r"(lo), "=r"(hi) : "l"(in))

__device__ __forceinline__ uint32_t smem_u32(const void* p) {
    uint32_t a;
    asm("{ .reg .u64 t; cvta.to.shared.u64 t, %1; cvt.u32.u64 %0, t; }" : "=r"(a) : "l"(p));
    return a;
}
__device__ __forceinline__ void ldsm_x4(unsigned r[4], uint32_t addr) {
    asm volatile("ldmatrix.sync.aligned.m8n8.x4.shared.b16 {%0,%1,%2,%3}, [%4];"
        : "=r"(r[0]), "=r"(r[1]), "=r"(r[2]), "=r"(r[3]) : "r"(addr));
}
__device__ __forceinline__ void ldsm_x2(unsigned r[2], uint32_t addr) {
    asm volatile("ldmatrix.sync.aligned.m8n8.x2.shared.b16 {%0,%1}, [%2];"
        : "=r"(r[0]), "=r"(r[1]) : "r"(addr));
}
__device__ __forceinline__ void mma_bf16(float d[4], const unsigned a[4], const unsigned b[2]) {
    asm volatile("mma.sync.aligned.m16n8k16.row.col.f32.bf16.bf16.f32 "
        "{%0,%1,%2,%3}, {%4,%5,%6,%7}, {%8,%9}, {%0,%1,%2,%3};"
        : "+f"(d[0]), "+f"(d[1]), "+f"(d[2]), "+f"(d[3])
        : "r"(a[0]), "r"(a[1]), "r"(a[2]), "r"(a[3]), "r"(b[0]), "r"(b[1]));
}
__device__ __forceinline__ uint32_t stoff(int r, int g) {
    return (uint32_t)(r * 64 + ((g ^ ((r >> 1) & 3)) << 4));
}

// ---------------------------------------------------------------------------
// Scratch
// ---------------------------------------------------------------------------
__device__ __align__(16) float g_Q[(size_t)BH_ * T_ * DH_];
__device__ __align__(16) float g_K[(size_t)BH_ * T_ * DH_];
__device__ __align__(16) float g_V[(size_t)BH_ * T_ * DH_];
__device__ __align__(16) float g_S[(size_t)BH_ * T_ * T_];
__device__ __align__(16) float g_AO[(size_t)B_ * T_ * D_];
__device__ __align__(16) __nv_bfloat16 g_Xs [(size_t)4096 * 3072];  // (h,h,l)
__device__ __align__(16) __nv_bfloat16 g_AOs[(size_t)4096 * 3072];  // (h,h,l)
__device__ __align__(16) __nv_bfloat16 g_Wvs[(size_t)1024 * 3072];  // (h,l,h)
__device__ __align__(16) __nv_bfloat16 g_Wos[(size_t)1024 * 3072];  // (h,l,h)

// ---------------------------------------------------------------------------
// Split: fp32 [R,1024] -> bf16 [R,3072]; AHL=1 (h,h,l), AHL=0 (h,l,h)
// ---------------------------------------------------------------------------
template<int AHL>
__global__ __launch_bounds__(256)
void split_bf16(const float* __restrict__ in, __nv_bfloat16* __restrict__ outp)
{
    const int idx = blockIdx.x * 256 + threadIdx.x;
    const int r = idx >> 8;
    const int c = (idx & 255) * 4;
    float4 v = *(const float4*)(in + (size_t)r * 1024 + c);
    __nv_bfloat162 h01 = __floats2bfloat162_rn(v.x, v.y);
    __nv_bfloat162 h23 = __floats2bfloat162_rn(v.z, v.w);
    float lx = v.x - __bfloat162float(h01.x);
    float ly = v.y - __bfloat162float(h01.y);
    float lz = v.z - __bfloat162float(h23.x);
    float lw = v.w - __bfloat162float(h23.y);
    __nv_bfloat162 l01 = __floats2bfloat162_rn(lx, ly);
    __nv_bfloat162 l23 = __floats2bfloat162_rn(lz, lw);
    __nv_bfloat162* o0 = (__nv_bfloat162*)(outp + (size_t)r * 3072 + c);
    __nv_bfloat162* o1 = (__nv_bfloat162*)(outp + (size_t)r * 3072 + 1024 + c);
    __nv_bfloat162* o2 = (__nv_bfloat162*)(outp + (size_t)r * 3072 + 2048 + c);
    o0[0] = h01; o0[1] = h23;
    if (AHL) { o1[0] = h01; o1[1] = h23; o2[0] = l01; o2[1] = l23; }
    else     { o1[0] = l01; o1[1] = l23; o2[0] = h01; o2[1] = h23; }
}

// ---------------------------------------------------------------------------
// HMMA bf16 GEMM (R8 version, static smem, sync loads): C = A' @ B'^T
// ---------------------------------------------------------------------------
template<int EPI>   // 0: head-split, 1: +bias plain
__global__ __launch_bounds__(256, 2)
void gemm_bf16_mma(const __nv_bfloat16* __restrict__ A,
                   const __nv_bfloat16* __restrict__ Bm,
                   const float* __restrict__ bias, float* __restrict__ C)
{
    constexpr int KT = 3072;
    constexpr int KC = 32;
    constexpr int NC = KT / KC;
    constexpr uint32_t TILE = 128 * 64;
    __shared__ __align__(128) char sm[2][2][TILE];

    const int tid = threadIdx.x, lane = tid & 31, wid = tid >> 5;
    const int wr = wid >> 2, wc = wid & 3;
    const int m0 = blockIdx.y * 128, n0 = blockIdx.x * 128;
    const uint32_t sbase = smem_u32(&sm[0][0][0]);

    float acc[4][4][4];
#pragma unroll
    for (int mb = 0; mb < 4; mb++)
#pragma unroll
        for (int nb = 0; nb < 4; nb++)
#pragma unroll
            for (int e = 0; e < 4; e++) acc[mb][nb][e] = 0.f;

    const int aRow = (lane & 15), aG = (lane >> 4) & 1;
    const int bRow = (lane & 7),  bG = (lane >> 3) & 1;

#pragma unroll
    for (int j = 0; j < 2; j++) {
        int p = tid + j * 256;
        int r = p >> 2, g = p & 3;
        *(uint4*)(&sm[0][0][0] + stoff(r, g)) = *(const uint4*)(A  + (size_t)(m0 + r) * KT + g * 8);
        *(uint4*)(&sm[0][1][0] + stoff(r, g)) = *(const uint4*)(Bm + (size_t)(n0 + r) * KT + g * 8);
    }
    __syncthreads();

    for (int c = 0; c < NC; c++) {
        const int buf = c & 1;
        if (c + 1 < NC) {
            const int ks = (c + 1) * KC;
            const int nb_ = buf ^ 1;
#pragma unroll
            for (int j = 0; j < 2; j++) {
                int p = tid + j * 256;
                int r = p >> 2, g = p & 3;
                *(uint4*)(&sm[nb_][0][0] + stoff(r, g)) = *(const uint4*)(A  + (size_t)(m0 + r) * KT + ks + g * 8);
                *(uint4*)(&sm[nb_][1][0] + stoff(r, g)) = *(const uint4*)(Bm + (size_t)(n0 + r) * KT + ks + g * 8);
            }
        }
        const uint32_t Ab = sbase + (uint32_t)buf * (2 * TILE);
        const uint32_t Bb = Ab + TILE;
#pragma unroll
        for (int s16 = 0; s16 < 2; s16++) {
            unsigned bfr[4][2];
#pragma unroll
            for (int nb = 0; nb < 4; nb++) {
                int r = 32 * wc + 8 * nb + bRow;
                ldsm_x2(bfr[nb], Bb + stoff(r, s16 * 2 + bG));
            }
#pragma unroll
            for (int mb = 0; mb < 4; mb++) {
                unsigned af[4];
                int r = 64 * wr + 16 * mb + aRow;
                ldsm_x4(af, Ab + stoff(r, s16 * 2 + aG));
#pragma unroll
                for (int nb = 0; nb < 4; nb++)
                    mma_bf16(acc[mb][nb], af, bfr[nb]);
            }
        }
        __syncthreads();
    }

#pragma unroll
    for (int mb = 0; mb < 4; mb++) {
        const int mlo = m0 + 64 * wr + 16 * mb + (lane >> 2);
#pragma unroll
        for (int nb = 0; nb < 4; nb++) {
            const int n = n0 + 32 * wc + 8 * nb + (lane & 3) * 2;
            float2 lo = make_float2(acc[mb][nb][0], acc[mb][nb][1]);
            float2 hi = make_float2(acc[mb][nb][2], acc[mb][nb][3]);
            if (EPI == 1) {
                float bx = bias[n], by = bias[n + 1];
                lo.x += bx; lo.y += by; hi.x += bx; hi.y += by;
                *(float2*)(C + (size_t)mlo * 1024 + n) = lo;
                *(float2*)(C + (size_t)(mlo + 8) * 1024 + n) = hi;
            } else {
                const int h = n >> 6, inner = n & 63;
                const int bb0 = mlo >> 11, t0v = mlo & (T_ - 1);
                const int bb1 = (mlo + 8) >> 11, t1v = (mlo + 8) & (T_ - 1);
                *(float2*)(C + (((size_t)(bb0 * H_ + h) * T_ + t0v) * DH_ + inner)) = lo;
                *(float2*)(C + (((size_t)(bb1 * H_ + h) * T_ + t1v) * DH_ + inner)) = hi;
            }
        }
    }
}

// ---------------------------------------------------------------------------
// SIMT FFMA2 GEMM (Q, K projections + scores) — BIT-IDENTICAL to R8
// ---------------------------------------------------------------------------
#define EPI_HEADS 2
#define EPI_SCALE 3

template<int EPI>
__global__ __launch_bounds__(256)
void gemm_abt(const float* __restrict__ A, const float* __restrict__ Bm,
              float* __restrict__ C, int M, int N, int K,
              long strideA, long strideB, long strideC)
{
    const float* Ab = A + (long)blockIdx.z * strideA;
    const float* Bb = Bm + (long)blockIdx.z * strideB;
    float* Cb = C + (long)blockIdx.z * strideC;

    __shared__ __align__(16) float AsT[16][128];
    __shared__ __align__(16) float BsT[16][128];

    const int tid = threadIdx.x;
    const int tx = tid & 15;
    const int ty = tid >> 4;
    const int m0 = blockIdx.y * 128;
    const int n0 = blockIdx.x * 128;

    unsigned long long acc2[8][4];
#pragma unroll
    for (int i = 0; i < 8; i++)
#pragma unroll
        for (int j = 0; j < 4; j++) acc2[i][j] = 0ull;

    for (int k0 = 0; k0 < K; k0 += 16) {
#pragma unroll
        for (int i = 0; i < 2; i++) {
            int idx  = tid * 2 + i;
            int row  = idx >> 2;
            int col4 = (idx & 3) * 4;
            float4 va = *(const float4*)(Ab + (long)(m0 + row) * K + k0 + col4);
            AsT[col4 + 0][row] = va.x;
            AsT[col4 + 1][row] = va.y;
            AsT[col4 + 2][row] = va.z;
            AsT[col4 + 3][row] = va.w;
            float4 vb = *(const float4*)(Bb + (long)(n0 + row) * K + k0 + col4);
            BsT[col4 + 0][row] = vb.x;
            BsT[col4 + 1][row] = vb.y;
            BsT[col4 + 2][row] = vb.z;
            BsT[col4 + 3][row] = vb.w;
        }
        __syncthreads();
#pragma unroll
        for (int k = 0; k < 16; k++) {
            float a[8];
            *(float4*)&a[0] = *(const float4*)&AsT[k][ty * 8];
            *(float4*)&a[4] = *(const float4*)&AsT[k][ty * 8 + 4];
            ulonglong2 b01 = *(const ulonglong2*)&BsT[k][tx * 8];
            ulonglong2 b23 = *(const ulonglong2*)&BsT[k][tx * 8 + 4];
#pragma unroll
            for (int i = 0; i < 8; i++) {
                unsigned long long ad;
                PACK_DUP_F32X2(ad, a[i]);
                FMA_F32X2(acc2[i][0], ad, b01.x, acc2[i][0]);
                FMA_F32X2(acc2[i][1], ad, b01.y, acc2[i][1]);
                FMA_F32X2(acc2[i][2], ad, b23.x, acc2[i][2]);
                FMA_F32X2(acc2[i][3], ad, b23.y, acc2[i][3]);
            }
        }
        __syncthreads();
    }

#pragma unroll
    for (int i = 0; i < 8; i++) {
        int m = m0 + ty * 8 + i;
#pragma unroll
        for (int jp = 0; jp < 4; jp += 2) {
            int n = n0 + tx * 8 + jp * 2;
            unsigned r0, r1, r2, r3;
            UNPACK_F32X2_(r0, r1, acc2[i][jp]);
            UNPACK_F32X2_(r2, r3, acc2[i][jp + 1]);
            float4 r = make_float4(__uint_as_float(r0), __uint_as_float(r1),
                                   __uint_as_float(r2), __uint_as_float(r3));
            if (EPI == EPI_SCALE) {
                r.x *= 0.125f; r.y *= 0.125f; r.z *= 0.125f; r.w *= 0.125f;
                *(float4*)(Cb + (long)m * N + n) = r;
            } else {
                int bb = m >> 11, t = m & (T_ - 1);
                int h = n >> 6, inner = n & (DH_ - 1);
                float* dst = Cb + (((long)(bb * H_ + h) * T_ + t) * DH_ + inner);
                *(float4*)dst = r;
            }
        }
    }
}

// ---------------------------------------------------------------------------
// Top-k radix select + softmax + sparse AV (R8 kernel + bh_base offset)
// ---------------------------------------------------------------------------
__device__ __forceinline__ unsigned uencode(float f) {
    unsigned b = __float_as_uint(f);
    return (b & 0x80000000u) ? ~b : (b | 0x80000000u);
}
__device__ __forceinline__ float udecode(unsigned u) {
    unsigned b = (u & 0x80000000u) ? (u & 0x7fffffffu) : ~u;
    return __uint_as_float(b);
}

__global__ __launch_bounds__(128)
void topk_softmax_av(const float* __restrict__ S, const float* __restrict__ V,
                     float* __restrict__ O, int bh_base)
{
    __shared__ int      hist[256];
    __shared__ int      s_list[128];
    __shared__ float    s_s[128];
    __shared__ float    s_part[128];
    __shared__ unsigned s_prefix;
    __shared__ int      s_kp;
    __shared__ int      s_cnt;
    __shared__ float    s_inv;

    const long row = blockIdx.x;
    const int bhl = (int)(row >> 11);
    const int bh = bh_base + bhl;
    const int tq = (int)(row & (T_ - 1));
    const float* Srow = S + row * T_;
    const int tid = threadIdx.x;

    if (tid == 0) s_cnt = 0;

    unsigned uloc[16];
#pragma unroll
    for (int i = 0; i < 16; i++)
        uloc[i] = uencode(Srow[tid + i * 128]);

    unsigned prefix = 0;
    int kprime = TOPK_;
#pragma unroll
    for (int level = 3; level >= 0; --level) {
        const int sh = level * 8;
        hist[tid] = 0;
        hist[tid + 128] = 0;
        __syncthreads();
        if (level == 3) {
#pragma unroll
            for (int i = 0; i < 16; i++)
                atomicAdd(&hist[uloc[i] >> 24], 1);
        } else {
            const unsigned hip = prefix >> (sh + 8);
#pragma unroll
            for (int i = 0; i < 16; i++) {
                unsigned u = uloc[i];
                if ((u >> (sh + 8)) == hip)
                    atomicAdd(&hist[(u >> sh) & 0xFFu], 1);
            }
        }
        __syncthreads();
        if (tid < 32) {
            const int base = tid * 8;
            int s = 0;
#pragma unroll
            for (int j = 0; j < 8; j++) s += hist[base + j];
            int suf = s;
#pragma unroll
            for (int off = 1; off < 32; off <<= 1) {
                int o = __shfl_down_sync(0xffffffffu, suf, off);
                if (tid + off < 32) suf += o;
            }
            int sufnext = __shfl_down_sync(0xffffffffu, suf, 1);
            if (tid == 31) sufnext = 0;
            unsigned mk = __ballot_sync(0xffffffffu, suf >= kprime);
            int lsel = 31 - __clz(mk);
            if (tid == lsel) {
                int running = sufnext;
                int b = base + 7;
                for (; b >= base; --b) {
                    int h = hist[b];
                    if (running + h >= kprime) break;
                    running += h;
                }
                s_prefix = prefix | ((unsigned)b << sh);
                s_kp = kprime - running;
            }
        }
        __syncthreads();
        prefix = s_prefix;
        kprime = s_kp;
    }
    const unsigned uthr = prefix;

#pragma unroll
    for (int i = 0; i < 16; i++) {
        unsigned u = uloc[i];
        if (u >= uthr) {
            int pos = atomicAdd(&s_cnt, 1);
            if (pos < 128) {
                s_list[pos] = tid + i * 128;
                s_s[pos] = udecode(u);
            }
        }
    }
    __syncthreads();
    const int cnt = min(s_cnt, 128);

    if (tid < 32) {
        float m = -3.4e38f;
        for (int e = tid; e < cnt; e += 32) m = fmaxf(m, s_s[e]);
#pragma unroll
        for (int off = 16; off; off >>= 1)
            m = fmaxf(m, __shfl_xor_sync(0xffffffffu, m, off));
        float sum = 0.f;
        for (int e = tid; e < cnt; e += 32) {
            float p = __expf(s_s[e] - m);
            s_s[e] = p;
            sum += p;
        }
#pragma unroll
        for (int off = 16; off; off >>= 1)
            sum += __shfl_xor_sync(0xffffffffu, sum, off);
        if (tid == 0) s_inv = 1.f / sum;
    }
    __syncthreads();

    {
        const int dim = tid & 63;
        const int half = tid >> 6;
        const float* Vb = V + (long)bhl * T_ * DH_;
        float acc = 0.f;
        for (int e = half; e < cnt; e += 2)
            acc += s_s[e] * Vb[(long)s_list[e] * DH_ + dim];
        s_part[tid] = acc;
    }
    __syncthreads();
    if (tid < DH_) {
        const int bb = bh >> 4, h = bh & (H_ - 1);
        float o = (s_part[tid] + s_part[tid + 64]) * s_inv;
        O[((long)(bb * T_ + tq)) * D_ + h * DH_ + tid] = o;
    }
}

// ---------------------------------------------------------------------------
// Launch — multi-stream DAG, fine-grained bh chunks (L2-resident S slices)
// ---------------------------------------------------------------------------
#define NCHUNK 16
#define BH_PER (BH_ / NCHUNK)   // 2

extern "C" void kernel_launch(void* const* d_in, const int* in_sizes, int n_in,
                              void* d_out, int out_size)
{
    const float* x    = (const float*)d_in[0];
    const float* Wq   = (const float*)d_in[1];
    const float* Wk   = (const float*)d_in[2];
    const float* Wv   = (const float*)d_in[3];
    const float* Wo_w = (const float*)d_in[4];
    const float* Wo_b = (const float*)d_in[5];
    float* out = (float*)d_out;

    float *pQ, *pK, *pV, *pS, *pAO;
    __nv_bfloat16 *pXs, *pAOs, *pWvs, *pWos;
    cudaGetSymbolAddress((void**)&pQ,  g_Q);
    cudaGetSymbolAddress((void**)&pK,  g_K);
    cudaGetSymbolAddress((void**)&pV,  g_V);
    cudaGetSymbolAddress((void**)&pS,  g_S);
    cudaGetSymbolAddress((void**)&pAO, g_AO);
    cudaGetSymbolAddress((void**)&pXs,  g_Xs);
    cudaGetSymbolAddress((void**)&pAOs, g_AOs);
    cudaGetSymbolAddress((void**)&pWvs, g_Wvs);
    cudaGetSymbolAddress((void**)&pWos, g_Wos);

    static cudaStream_t sB = nullptr, sC = nullptr;
    static cudaEvent_t e0, eV, eS[NCHUNK], eT;
    if (!sB) {
        cudaStreamCreateWithFlags(&sB, cudaStreamNonBlocking);
        cudaStreamCreateWithFlags(&sC, cudaStreamNonBlocking);
        cudaEventCreateWithFlags(&e0, cudaEventDisableTiming);
        cudaEventCreateWithFlags(&eV, cudaEventDisableTiming);
        for (int i = 0; i < NCHUNK; i++)
            cudaEventCreateWithFlags(&eS[i], cudaEventDisableTiming);
        cudaEventCreateWithFlags(&eT, cudaEventDisableTiming);
    }

    const int M = B_ * T_;   // 4096

    cudaEventRecord(e0, 0);
    cudaStreamWaitEvent(sB, e0, 0);

    // Stream B: splits + V projection (tensor pipe)
    split_bf16<1><<<4096, 256, 0, sB>>>(x, pXs);
    split_bf16<0><<<1024, 256, 0, sB>>>(Wv, pWvs);
    split_bf16<0><<<1024, 256, 0, sB>>>(Wo_w, pWos);
    {
        dim3 grid(D_ / 128, M / 128, 1);
        gemm_bf16_mma<0><<<grid, 256, 0, sB>>>(pXs, pWvs, nullptr, pV);
    }
    cudaEventRecord(eV, sB);

    // Main stream: Q, K projections (fp32 FFMA2, selection-critical)
    {
        dim3 grid(D_ / 128, M / 128, 1);
        gemm_abt<EPI_HEADS><<<grid, 256>>>(x, Wq, pQ, M, D_, D_, 0, 0, 0);
        gemm_abt<EPI_HEADS><<<grid, 256>>>(x, Wk, pK, M, D_, D_, 0, 0, 0);
    }

    // Scores chunked over bh; topk chunk i overlaps scores chunk i+1,
    // reading its 33.5MB S slice from L2.
    cudaStreamWaitEvent(sC, eV, 0);
    for (int c = 0; c < NCHUNK; c++) {
        const long boff = (long)c * BH_PER;
        dim3 grid(T_ / 128, T_ / 128, BH_PER);
        gemm_abt<EPI_SCALE><<<grid, 256>>>(pQ + boff * T_ * DH_, pK + boff * T_ * DH_,
                                           pS + boff * T_ * T_, T_, T_, DH_,
                                           (long)T_ * DH_, (long)T_ * DH_,
                                           (long)T_ * T_);
        cudaEventRecord(eS[c], 0);
        cudaStreamWaitEvent(sC, eS[c], 0);
        topk_softmax_av<<<BH_PER * T_, 128, 0, sC>>>(pS + boff * T_ * T_,
                                                     pV + boff * T_ * DH_,
                                                     pAO, (int)boff);
    }
    cudaEventRecord(eT, sC);
    cudaStreamWaitEvent(0, eT, 0);

    // Output projection (HMMA 3-term + bias)
    split_bf16<1><<<4096, 256>>>(pAO, pAOs);
    {
        dim3 grid(D_ / 128, M / 128, 1);
        gemm_bf16_mma<1><<<grid, 256>>>(pAOs, pWos, Wo_b, out);
    }
}

// round 13
// speedup vs baseline: 1.0799x; 1.0799x over previous
#include <cuda_runtime.h>
#include <cuda_bf16.h>
#include <cstdint>

// Problem constants
#define B_  2
#define T_  2048
#define D_  1024
#define H_  16
#define DH_ 64
#define TOPK_ 32
#define BH_ (B_*H_)

// Packed fp32x2 FMA
#define FMA_F32X2(d, a, b, c) \
    asm("fma.rn.f32x2 %0, %1, %2, %3;" : "=l"(d) : "l"(a), "l"(b), "l"(c))
#define PACK_DUP_F32X2(out, v) \
    asm("mov.b64 %0, {%1, %1};" : "=l"(out) : "r"(__float_as_uint(v)))
#define UNPACK_F32X2_(lo, hi, in) \
    asm("mov.b64 {%0, %1}, %2;" : "=r"(lo), "=r"(hi) : "l"(in))

__device__ __forceinline__ uint32_t smem_u32(const void* p) {
    uint32_t a;
    asm("{ .reg .u64 t; cvta.to.shared.u64 t, %1; cvt.u32.u64 %0, t; }" : "=r"(a) : "l"(p));
    return a;
}
__device__ __forceinline__ void ldsm_x4(unsigned r[4], uint32_t addr) {
    asm volatile("ldmatrix.sync.aligned.m8n8.x4.shared.b16 {%0,%1,%2,%3}, [%4];"
        : "=r"(r[0]), "=r"(r[1]), "=r"(r[2]), "=r"(r[3]) : "r"(addr));
}
__device__ __forceinline__ void ldsm_x2(unsigned r[2], uint32_t addr) {
    asm volatile("ldmatrix.sync.aligned.m8n8.x2.shared.b16 {%0,%1}, [%2];"
        : "=r"(r[0]), "=r"(r[1]) : "r"(addr));
}
__device__ __forceinline__ void mma_bf16(float d[4], const unsigned a[4], const unsigned b[2]) {
    asm volatile("mma.sync.aligned.m16n8k16.row.col.f32.bf16.bf16.f32 "
        "{%0,%1,%2,%3}, {%4,%5,%6,%7}, {%8,%9}, {%0,%1,%2,%3};"
        : "+f"(d[0]), "+f"(d[1]), "+f"(d[2]), "+f"(d[3])
        : "r"(a[0]), "r"(a[1]), "r"(a[2]), "r"(a[3]), "r"(b[0]), "r"(b[1]));
}
__device__ __forceinline__ uint32_t stoff(int r, int g) {
    return (uint32_t)(r * 64 + ((g ^ ((r >> 1) & 3)) << 4));
}

// ---------------------------------------------------------------------------
// Scratch
// ---------------------------------------------------------------------------
__device__ __align__(16) float g_Q[(size_t)BH_ * T_ * DH_];
__device__ __align__(16) float g_K[(size_t)BH_ * T_ * DH_];
__device__ __align__(16) float g_V[(size_t)BH_ * T_ * DH_];
__device__ __align__(16) __nv_bfloat16 g_Sb[(size_t)BH_ * T_ * T_];   // approx scores
__device__ __align__(16) float g_AO[(size_t)B_ * T_ * D_];
__device__ __align__(16) __nv_bfloat16 g_Xs [(size_t)4096 * 3072];  // (h,h,l)
__device__ __align__(16) __nv_bfloat16 g_AOs[(size_t)4096 * 3072];  // (h,h,l)
__device__ __align__(16) __nv_bfloat16 g_Wvs[(size_t)1024 * 3072];  // (h,l,h)
__device__ __align__(16) __nv_bfloat16 g_Wos[(size_t)1024 * 3072];  // (h,l,h)
__device__ __align__(16) __nv_bfloat16 g_Qs3[(size_t)BH_ * T_ * 192];
__device__ __align__(16) __nv_bfloat16 g_Ks3[(size_t)BH_ * T_ * 192];

// ---------------------------------------------------------------------------
// Split: fp32 [R,1024] -> bf16 [R,3072]; AHL=1 (h,h,l), AHL=0 (h,l,h)
// ---------------------------------------------------------------------------
template<int AHL>
__global__ __launch_bounds__(256)
void split_bf16(const float* __restrict__ in, __nv_bfloat16* __restrict__ outp)
{
    const int idx = blockIdx.x * 256 + threadIdx.x;
    const int r = idx >> 8;
    const int c = (idx & 255) * 4;
    float4 v = *(const float4*)(in + (size_t)r * 1024 + c);
    __nv_bfloat162 h01 = __floats2bfloat162_rn(v.x, v.y);
    __nv_bfloat162 h23 = __floats2bfloat162_rn(v.z, v.w);
    float lx = v.x - __bfloat162float(h01.x);
    float ly = v.y - __bfloat162float(h01.y);
    float lz = v.z - __bfloat162float(h23.x);
    float lw = v.w - __bfloat162float(h23.y);
    __nv_bfloat162 l01 = __floats2bfloat162_rn(lx, ly);
    __nv_bfloat162 l23 = __floats2bfloat162_rn(lz, lw);
    __nv_bfloat162* o0 = (__nv_bfloat162*)(outp + (size_t)r * 3072 + c);
    __nv_bfloat162* o1 = (__nv_bfloat162*)(outp + (size_t)r * 3072 + 1024 + c);
    __nv_bfloat162* o2 = (__nv_bfloat162*)(outp + (size_t)r * 3072 + 2048 + c);
    o0[0] = h01; o0[1] = h23;
    if (AHL) { o1[0] = h01; o1[1] = h23; o2[0] = l01; o2[1] = l23; }
    else     { o1[0] = l01; o1[1] = l23; o2[0] = h01; o2[1] = h23; }
}

// Split Q/K: fp32 [R,64] -> bf16 [R,192]; AHL=1 (h,h,l), AHL=0 (h,l,h)
template<int AHL>
__global__ __launch_bounds__(256)
void split_qk3(const float* __restrict__ in, __nv_bfloat16* __restrict__ outp)
{
    const int idx = blockIdx.x * 256 + threadIdx.x;
    const int r = idx >> 4;
    const int c = (idx & 15) * 4;
    float4 v = *(const float4*)(in + (size_t)r * 64 + c);
    __nv_bfloat162 h01 = __floats2bfloat162_rn(v.x, v.y);
    __nv_bfloat162 h23 = __floats2bfloat162_rn(v.z, v.w);
    float lx = v.x - __bfloat162float(h01.x);
    float ly = v.y - __bfloat162float(h01.y);
    float lz = v.z - __bfloat162float(h23.x);
    float lw = v.w - __bfloat162float(h23.y);
    __nv_bfloat162 l01 = __floats2bfloat162_rn(lx, ly);
    __nv_bfloat162 l23 = __floats2bfloat162_rn(lz, lw);
    __nv_bfloat162* o0 = (__nv_bfloat162*)(outp + (size_t)r * 192 + c);
    __nv_bfloat162* o1 = (__nv_bfloat162*)(outp + (size_t)r * 192 + 64 + c);
    __nv_bfloat162* o2 = (__nv_bfloat162*)(outp + (size_t)r * 192 + 128 + c);
    o0[0] = h01; o0[1] = h23;
    if (AHL) { o1[0] = h01; o1[1] = h23; o2[0] = l01; o2[1] = l23; }
    else     { o1[0] = l01; o1[1] = l23; o2[0] = h01; o2[1] = h23; }
}

// ---------------------------------------------------------------------------
// HMMA bf16 GEMM (R8 structure, runtime N/K + batching): C = A @ B^T
// EPI 0: head-split fp32 [BH,T,DH] (N==1024)
// EPI 1: +bias fp32 plain [M,1024]
// EPI 2: *0.125 -> bf16 plain [M,N]
// ---------------------------------------------------------------------------
template<int EPI>
__global__ __launch_bounds__(256, 2)
void gemm_bf16_mma(const __nv_bfloat16* __restrict__ Ag,
                   const __nv_bfloat16* __restrict__ Bg,
                   const float* __restrict__ bias, void* __restrict__ Cv,
                   int N, int K, long sA, long sB, long sC)
{
    const int NC = K >> 5;
    constexpr uint32_t TILE = 128 * 64;
    __shared__ __align__(128) char sm[2][2][TILE];

    const __nv_bfloat16* A = Ag + (size_t)blockIdx.z * sA;
    const __nv_bfloat16* Bm = Bg + (size_t)blockIdx.z * sB;

    const int tid = threadIdx.x, lane = tid & 31, wid = tid >> 5;
    const int wr = wid >> 2, wc = wid & 3;
    const int m0 = blockIdx.y * 128, n0 = blockIdx.x * 128;
    const uint32_t sbase = smem_u32(&sm[0][0][0]);

    float acc[4][4][4];
#pragma unroll
    for (int mb = 0; mb < 4; mb++)
#pragma unroll
        for (int nb = 0; nb < 4; nb++)
#pragma unroll
            for (int e = 0; e < 4; e++) acc[mb][nb][e] = 0.f;

    const int aRow = (lane & 15), aG = (lane >> 4) & 1;
    const int bRow = (lane & 7),  bG = (lane >> 3) & 1;

#pragma unroll
    for (int j = 0; j < 2; j++) {
        int p = tid + j * 256;
        int r = p >> 2, g = p & 3;
        *(uint4*)(&sm[0][0][0] + stoff(r, g)) = *(const uint4*)(A  + (size_t)(m0 + r) * K + g * 8);
        *(uint4*)(&sm[0][1][0] + stoff(r, g)) = *(const uint4*)(Bm + (size_t)(n0 + r) * K + g * 8);
    }
    __syncthreads();

    for (int c = 0; c < NC; c++) {
        const int buf = c & 1;
        if (c + 1 < NC) {
            const int ks = (c + 1) * 32;
            const int nb_ = buf ^ 1;
#pragma unroll
            for (int j = 0; j < 2; j++) {
                int p = tid + j * 256;
                int r = p >> 2, g = p & 3;
                *(uint4*)(&sm[nb_][0][0] + stoff(r, g)) = *(const uint4*)(A  + (size_t)(m0 + r) * K + ks + g * 8);
                *(uint4*)(&sm[nb_][1][0] + stoff(r, g)) = *(const uint4*)(Bm + (size_t)(n0 + r) * K + ks + g * 8);
            }
        }
        const uint32_t Ab = sbase + (uint32_t)buf * (2 * TILE);
        const uint32_t Bb = Ab + TILE;
#pragma unroll
        for (int s16 = 0; s16 < 2; s16++) {
            unsigned bfr[4][2];
#pragma unroll
            for (int nb = 0; nb < 4; nb++) {
                int r = 32 * wc + 8 * nb + bRow;
                ldsm_x2(bfr[nb], Bb + stoff(r, s16 * 2 + bG));
            }
#pragma unroll
            for (int mb = 0; mb < 4; mb++) {
                unsigned af[4];
                int r = 64 * wr + 16 * mb + aRow;
                ldsm_x4(af, Ab + stoff(r, s16 * 2 + aG));
#pragma unroll
                for (int nb = 0; nb < 4; nb++)
                    mma_bf16(acc[mb][nb], af, bfr[nb]);
            }
        }
        __syncthreads();
    }

#pragma unroll
    for (int mb = 0; mb < 4; mb++) {
        const int mlo = m0 + 64 * wr + 16 * mb + (lane >> 2);
#pragma unroll
        for (int nb = 0; nb < 4; nb++) {
            const int n = n0 + 32 * wc + 8 * nb + (lane & 3) * 2;
            float2 lo = make_float2(acc[mb][nb][0], acc[mb][nb][1]);
            float2 hi = make_float2(acc[mb][nb][2], acc[mb][nb][3]);
            if (EPI == 1) {
                float* C = (float*)Cv;
                float bx = bias[n], by = bias[n + 1];
                lo.x += bx; lo.y += by; hi.x += bx; hi.y += by;
                *(float2*)(C + (size_t)mlo * N + n) = lo;
                *(float2*)(C + (size_t)(mlo + 8) * N + n) = hi;
            } else if (EPI == 2) {
                __nv_bfloat16* C = (__nv_bfloat16*)Cv + (size_t)blockIdx.z * sC;
                __nv_bfloat162 p0 = __floats2bfloat162_rn(lo.x * 0.125f, lo.y * 0.125f);
                __nv_bfloat162 p1 = __floats2bfloat162_rn(hi.x * 0.125f, hi.y * 0.125f);
                *(__nv_bfloat162*)(C + (size_t)mlo * N + n) = p0;
                *(__nv_bfloat162*)(C + (size_t)(mlo + 8) * N + n) = p1;
            } else {
                float* C = (float*)Cv;
                const int h = n >> 6, inner = n & 63;
                const int bb0 = mlo >> 11, t0v = mlo & (T_ - 1);
                const int bb1 = (mlo + 8) >> 11, t1v = (mlo + 8) & (T_ - 1);
                *(float2*)(C + (((size_t)(bb0 * H_ + h) * T_ + t0v) * DH_ + inner)) = lo;
                *(float2*)(C + (((size_t)(bb1 * H_ + h) * T_ + t1v) * DH_ + inner)) = hi;
            }
        }
    }
}

// ---------------------------------------------------------------------------
// SIMT FFMA2 GEMM — Q, K projections (selection-critical, bit-identical R8)
// ---------------------------------------------------------------------------
__global__ __launch_bounds__(256)
void gemm_abt_heads(const float* __restrict__ A, const float* __restrict__ Bm,
                    float* __restrict__ C, int M, int N, int K)
{
    __shared__ __align__(16) float AsT[16][128];
    __shared__ __align__(16) float BsT[16][128];

    const int tid = threadIdx.x;
    const int tx = tid & 15;
    const int ty = tid >> 4;
    const int m0 = blockIdx.y * 128;
    const int n0 = blockIdx.x * 128;

    unsigned long long acc2[8][4];
#pragma unroll
    for (int i = 0; i < 8; i++)
#pragma unroll
        for (int j = 0; j < 4; j++) acc2[i][j] = 0ull;

    for (int k0 = 0; k0 < K; k0 += 16) {
#pragma unroll
        for (int i = 0; i < 2; i++) {
            int idx  = tid * 2 + i;
            int row  = idx >> 2;
            int col4 = (idx & 3) * 4;
            float4 va = *(const float4*)(A + (long)(m0 + row) * K + k0 + col4);
            AsT[col4 + 0][row] = va.x;
            AsT[col4 + 1][row] = va.y;
            AsT[col4 + 2][row] = va.z;
            AsT[col4 + 3][row] = va.w;
            float4 vb = *(const float4*)(Bm + (long)(n0 + row) * K + k0 + col4);
            BsT[col4 + 0][row] = vb.x;
            BsT[col4 + 1][row] = vb.y;
            BsT[col4 + 2][row] = vb.z;
            BsT[col4 + 3][row] = vb.w;
        }
        __syncthreads();
#pragma unroll
        for (int k = 0; k < 16; k++) {
            float a[8];
            *(float4*)&a[0] = *(const float4*)&AsT[k][ty * 8];
            *(float4*)&a[4] = *(const float4*)&AsT[k][ty * 8 + 4];
            ulonglong2 b01 = *(const ulonglong2*)&BsT[k][tx * 8];
            ulonglong2 b23 = *(const ulonglong2*)&BsT[k][tx * 8 + 4];
#pragma unroll
            for (int i = 0; i < 8; i++) {
                unsigned long long ad;
                PACK_DUP_F32X2(ad, a[i]);
                FMA_F32X2(acc2[i][0], ad, b01.x, acc2[i][0]);
                FMA_F32X2(acc2[i][1], ad, b01.y, acc2[i][1]);
                FMA_F32X2(acc2[i][2], ad, b23.x, acc2[i][2]);
                FMA_F32X2(acc2[i][3], ad, b23.y, acc2[i][3]);
            }
        }
        __syncthreads();
    }

#pragma unroll
    for (int i = 0; i < 8; i++) {
        int m = m0 + ty * 8 + i;
#pragma unroll
        for (int jp = 0; jp < 4; jp += 2) {
            int n = n0 + tx * 8 + jp * 2;
            unsigned r0, r1, r2, r3;
            UNPACK_F32X2_(r0, r1, acc2[i][jp]);
            UNPACK_F32X2_(r2, r3, acc2[i][jp + 1]);
            float4 r = make_float4(__uint_as_float(r0), __uint_as_float(r1),
                                   __uint_as_float(r2), __uint_as_float(r3));
            int bb = m >> 11, t = m & (T_ - 1);
            int h = n >> 6, inner = n & (DH_ - 1);
            float* dst = C + (((long)(bb * H_ + h) * T_ + t) * DH_ + inner);
            *(float4*)dst = r;
        }
    }
}

// ---------------------------------------------------------------------------
// Approx-select (16-bit radix on bf16 scores) + exact fp32 re-rank +
// softmax + sparse AV. One block (128 threads) per query row.
// ---------------------------------------------------------------------------
__device__ __forceinline__ int enc16(int b) {
    return (b & 0x8000) ? (~b & 0xFFFF) : (b | 0x8000);
}
__device__ __forceinline__ float dec16f(int u) {
    int b = (u & 0x8000) ? (u & 0x7FFF) : (~u & 0xFFFF);
    return __uint_as_float((unsigned)b << 16);
}

__global__ __launch_bounds__(128)
void topk_rerank_av(const __nv_bfloat16* __restrict__ S,
                    const float* __restrict__ Qf, const float* __restrict__ Kf,
                    const float* __restrict__ V, float* __restrict__ O,
                    int bh_base)
{
    __shared__ int      hist[256];
    __shared__ float    s_q[64];
    __shared__ int      s_list[128];
    __shared__ float    s_v[128];
    __shared__ float    s_p[128];
    __shared__ float    s_part[128];
    __shared__ int      s_prefix;
    __shared__ int      s_kp;
    __shared__ int      s_cnt;
    __shared__ float    s_inv;

    const long row = blockIdx.x;
    const int bhl = (int)(row >> 11);
    const int bh = bh_base + bhl;
    const int tq = (int)(row & (T_ - 1));
    const int tid = threadIdx.x;

    if (tid == 0) s_cnt = 0;
    if (tid < 16)
        *(float4*)&s_q[tid * 4] =
            *(const float4*)(Qf + (((size_t)bhl * T_ + tq) * DH_) + tid * 4);

    // load 16 bf16 approx scores per thread (2 x uint4, coalesced)
    const uint4* S4 = (const uint4*)(S + row * T_);
    int us[16];
    int ibase[2];
#pragma unroll
    for (int i = 0; i < 2; i++) {
        uint4 w = S4[tid + i * 128];
        ibase[i] = (tid + i * 128) * 8;
        unsigned ws[4] = {w.x, w.y, w.z, w.w};
#pragma unroll
        for (int j = 0; j < 4; j++) {
            us[i * 8 + j * 2 + 0] = enc16((int)(ws[j] & 0xFFFFu));
            us[i * 8 + j * 2 + 1] = enc16((int)(ws[j] >> 16));
        }
    }

    // 2-level radix select (exact kth largest of bf16 values, k=32)
    int prefix = 0, kprime = TOPK_;
#pragma unroll
    for (int level = 1; level >= 0; --level) {
        const int sh = level * 8;
        hist[tid] = 0;
        hist[tid + 128] = 0;
        __syncthreads();
        const int hip = prefix >> (sh + 8);
#pragma unroll
        for (int i = 0; i < 16; i++) {
            int u = us[i];
            if ((u >> (sh + 8)) == hip)
                atomicAdd(&hist[(u >> sh) & 0xFF], 1);
        }
        __syncthreads();
        if (tid < 32) {
            const int base = tid * 8;
            int s = 0;
#pragma unroll
            for (int j = 0; j < 8; j++) s += hist[base + j];
            int suf = s;
#pragma unroll
            for (int off = 1; off < 32; off <<= 1) {
                int o = __shfl_down_sync(0xffffffffu, suf, off);
                if (tid + off < 32) suf += o;
            }
            int sufnext = __shfl_down_sync(0xffffffffu, suf, 1);
            if (tid == 31) sufnext = 0;
            unsigned mk = __ballot_sync(0xffffffffu, suf >= kprime);
            int lsel = 31 - __clz(mk);
            if (tid == lsel) {
                int running = sufnext;
                int b = base + 7;
                for (; b >= base; --b) {
                    int h = hist[b];
                    if (running + h >= kprime) break;
                    running += h;
                }
                s_prefix = prefix | (b << sh);
                s_kp = kprime - running;
            }
        }
        __syncthreads();
        prefix = s_prefix;
        kprime = s_kp;
    }

    // widened acceptance threshold (margin covers approx error soundly)
    const float thrf = dec16f(prefix) - 0.05f;
    const int uthr_w = enc16((int)(__bfloat16_as_ushort(__float2bfloat16(thrf))));

    // compact candidates
#pragma unroll
    for (int i = 0; i < 16; i++) {
        if (us[i] >= uthr_w) {
            int pos = atomicAdd(&s_cnt, 1);
            if (pos < 128)
                s_list[pos] = ibase[i >> 3] + (i & 7);
        }
    }
    __syncthreads();
    const int cnt = min(s_cnt, 128);

    // exact fp32 recompute for candidates
    if (tid < cnt) {
        const float* Kr = Kf + ((size_t)bhl * T_ + s_list[tid]) * DH_;
        float acc = 0.f;
#pragma unroll
        for (int k4 = 0; k4 < 16; k4++) {
            float4 kv = *(const float4*)(Kr + k4 * 4);
            acc = fmaf(s_q[k4 * 4 + 0], kv.x, acc);
            acc = fmaf(s_q[k4 * 4 + 1], kv.y, acc);
            acc = fmaf(s_q[k4 * 4 + 2], kv.z, acc);
            acc = fmaf(s_q[k4 * 4 + 3], kv.w, acc);
        }
        s_v[tid] = acc * 0.125f;
    }
    __syncthreads();

    // exact rank among candidates; keep rank<32 (ties kept, matching ref)
    float m = -3.4e38f;
    for (int j = 0; j < cnt; j++) m = fmaxf(m, s_v[j]);
    if (tid < cnt) {
        const float v = s_v[tid];
        int c = 0;
        for (int j = 0; j < cnt; j++) c += (s_v[j] > v);
        s_p[tid] = (c < TOPK_) ? __expf(v - m) : 0.f;
    }
    __syncthreads();

    // softmax denominator (warp 0)
    if (tid < 32) {
        float sum = 0.f;
        for (int e = tid; e < cnt; e += 32) sum += s_p[e];
#pragma unroll
        for (int off = 16; off; off >>= 1)
            sum += __shfl_xor_sync(0xffffffffu, sum, off);
        if (tid == 0) s_inv = 1.f / sum;
    }
    __syncthreads();

    // sparse P @ V
    {
        const int dim = tid & 63;
        const int half = tid >> 6;
        const float* Vb = V + (size_t)bhl * T_ * DH_;
        float acc = 0.f;
        for (int e = half; e < cnt; e += 2)
            acc += s_p[e] * Vb[(size_t)s_list[e] * DH_ + dim];
        s_part[tid] = acc;
    }
    __syncthreads();
    if (tid < DH_) {
        const int bb = bh >> 4, h = bh & (H_ - 1);
        float o = (s_part[tid] + s_part[tid + 64]) * s_inv;
        O[((size_t)(bb * T_ + tq)) * D_ + h * DH_ + tid] = o;
    }
}

// ---------------------------------------------------------------------------
// Launch
// ---------------------------------------------------------------------------
#define NCHUNK 4
#define BH_PER (BH_ / NCHUNK)   // 8

extern "C" void kernel_launch(void* const* d_in, const int* in_sizes, int n_in,
                              void* d_out, int out_size)
{
    const float* x    = (const float*)d_in[0];
    const float* Wq   = (const float*)d_in[1];
    const float* Wk   = (const float*)d_in[2];
    const float* Wv   = (const float*)d_in[3];
    const float* Wo_w = (const float*)d_in[4];
    const float* Wo_b = (const float*)d_in[5];
    float* out = (float*)d_out;

    float *pQ, *pK, *pV, *pAO;
    __nv_bfloat16 *pSb, *pXs, *pAOs, *pWvs, *pWos, *pQs3, *pKs3;
    cudaGetSymbolAddress((void**)&pQ,   g_Q);
    cudaGetSymbolAddress((void**)&pK,   g_K);
    cudaGetSymbolAddress((void**)&pV,   g_V);
    cudaGetSymbolAddress((void**)&pSb,  g_Sb);
    cudaGetSymbolAddress((void**)&pAO,  g_AO);
    cudaGetSymbolAddress((void**)&pXs,  g_Xs);
    cudaGetSymbolAddress((void**)&pAOs, g_AOs);
    cudaGetSymbolAddress((void**)&pWvs, g_Wvs);
    cudaGetSymbolAddress((void**)&pWos, g_Wos);
    cudaGetSymbolAddress((void**)&pQs3, g_Qs3);
    cudaGetSymbolAddress((void**)&pKs3, g_Ks3);

    static cudaStream_t sB = nullptr, sC = nullptr;
    static cudaEvent_t e0, eV, eS[NCHUNK], eT;
    if (!sB) {
        cudaStreamCreateWithFlags(&sB, cudaStreamNonBlocking);
        cudaStreamCreateWithFlags(&sC, cudaStreamNonBlocking);
        cudaEventCreateWithFlags(&e0, cudaEventDisableTiming);
        cudaEventCreateWithFlags(&eV, cudaEventDisableTiming);
        for (int i = 0; i < NCHUNK; i++)
            cudaEventCreateWithFlags(&eS[i], cudaEventDisableTiming);
        cudaEventCreateWithFlags(&eT, cudaEventDisableTiming);
    }

    const int M = B_ * T_;   // 4096

    cudaEventRecord(e0, 0);
    cudaStreamWaitEvent(sB, e0, 0);

    // Stream B: splits + V projection (tensor pipe)
    split_bf16<1><<<4096, 256, 0, sB>>>(x, pXs);
    split_bf16<0><<<1024, 256, 0, sB>>>(Wv, pWvs);
    split_bf16<0><<<1024, 256, 0, sB>>>(Wo_w, pWos);
    {
        dim3 grid(D_ / 128, M / 128, 1);
        gemm_bf16_mma<0><<<grid, 256, 0, sB>>>(pXs, pWvs, nullptr, pV, D_, 3072, 0, 0, 0);
    }
    cudaEventRecord(eV, sB);

    // Main stream: Q, K projections (fp32 FFMA2, selection-critical)
    {
        dim3 grid(D_ / 128, M / 128, 1);
        gemm_abt_heads<<<grid, 256>>>(x, Wq, pQ, M, D_, D_);
        gemm_abt_heads<<<grid, 256>>>(x, Wk, pK, M, D_, D_);
    }
    // 3-term splits of Q, K for approx scores
    split_qk3<1><<<4096, 256>>>(pQ, pQs3);
    split_qk3<0><<<4096, 256>>>(pK, pKs3);

    // Approx scores (bf16 HMMA) chunked; rerank-topk chunk i overlaps chunk i+1
    cudaStreamWaitEvent(sC, eV, 0);
    for (int c = 0; c < NCHUNK; c++) {
        const long boff = (long)c * BH_PER;
        dim3 grid(T_ / 128, T_ / 128, BH_PER);
        gemm_bf16_mma<2><<<grid, 256>>>(pQs3 + boff * T_ * 192,
                                        pKs3 + boff * T_ * 192,
                                        nullptr, pSb + boff * T_ * T_,
                                        T_, 192,
                                        (long)T_ * 192, (long)T_ * 192,
                                        (long)T_ * T_);
        cudaEventRecord(eS[c], 0);
        cudaStreamWaitEvent(sC, eS[c], 0);
        topk_rerank_av<<<BH_PER * T_, 128, 0, sC>>>(pSb + boff * T_ * T_,
                                                    pQ + boff * T_ * DH_,
                                                    pK + boff * T_ * DH_,
                                                    pV + boff * T_ * DH_,
                                                    pAO, (int)boff);
    }
    cudaEventRecord(eT, sC);
    cudaStreamWaitEvent(0, eT, 0);

    // Output projection (HMMA 3-term + bias)
    split_bf16<1><<<4096, 256>>>(pAO, pAOs);
    {
        dim3 grid(D_ / 128, M / 128, 1);
        gemm_bf16_mma<1><<<grid, 256>>>(pAOs, pWos, Wo_b, out, D_, 3072, 0, 0, 0);
    }
}